// round 1
// baseline (speedup 1.0000x reference)
#include <cuda_runtime.h>
#include <mma.h>

using namespace nvcuda;

#define LNUM   4
#define BTOK   16384
#define DIN    2048
#define DOUT   2048
#define TILE_M 128
#define TILE_N 128
#define TILE_K 32
#define MAX_TILES (BTOK / TILE_M + LNUM)   // 132

// ---------------- scratch (device globals; no allocation allowed) ----------
__device__ int      g_counts[LNUM];
__device__ int      g_offsets[LNUM + 1];
__device__ int      g_cursor[LNUM];
__device__ int      g_perm[BTOK];
__device__ int      g_tile_expert[MAX_TILES];
__device__ int      g_tile_row[MAX_TILES];
__device__ int      g_ntiles;
__device__ unsigned g_odd_or;
__device__ int      g_is64;

// ---------------- tiny prologue kernels -----------------------------------
__global__ void k_init() {
    int t = threadIdx.x;
    if (t < LNUM) { g_counts[t] = 0; g_cursor[t] = 0; }
    if (t == 0)   { g_odd_or = 0u; }
}

// Detect whether layer_idx is int64 or int32. In int64 little-endian layout,
// the odd 32-bit words (within the first BTOK words, which exist in both
// layouts) are all zero; for random int32 values in [0,4) that is
// astronomically unlikely. If everything is zero both interpretations agree.
__global__ void k_detect(const unsigned* idx_words) {
    unsigned acc = 0;
    for (int j = 1 + 2 * (blockIdx.x * blockDim.x + threadIdx.x); j < BTOK;
         j += 2 * gridDim.x * blockDim.x)
        acc |= idx_words[j];
    if (acc) atomicOr(&g_odd_or, acc);
}

__global__ void k_detect_fin() { g_is64 = (g_odd_or == 0u) ? 1 : 0; }

__device__ __forceinline__ int read_expert(const void* idx, int j) {
    if (g_is64) return (int)((const long long*)idx)[j];
    return ((const int*)idx)[j];
}

__global__ void k_hist(const void* idx) {
    int j = blockIdx.x * blockDim.x + threadIdx.x;
    if (j < BTOK) atomicAdd(&g_counts[read_expert(idx, j)], 1);
}

__global__ void k_plan() {
    g_offsets[0] = 0;
    for (int e = 0; e < LNUM; e++) g_offsets[e + 1] = g_offsets[e] + g_counts[e];
    int nt = 0;
    for (int e = 0; e < LNUM; e++)
        for (int r = g_offsets[e]; r < g_offsets[e + 1]; r += TILE_M) {
            g_tile_expert[nt] = e;
            g_tile_row[nt] = r;
            nt++;
        }
    g_ntiles = nt;
}

__global__ void k_scatter(const void* idx) {
    int j = blockIdx.x * blockDim.x + threadIdx.x;
    if (j < BTOK) {
        int e = read_expert(idx, j);
        int p = atomicAdd(&g_cursor[e], 1);
        g_perm[g_offsets[e] + p] = j;
    }
}

// ---------------- grouped GEMM (tf32 wmma) ---------------------------------
// CTA: 128 (rows, gathered tokens of one expert) x 128 (out cols), K-tile 32.
// 8 warps, each 32x64 via 2x4 wmma m16n16k8 tf32 fragments, fp32 accumulate.
#define LDA 36      // 32 + 4 pad
#define LDB 132     // 128 + 4 pad
#define LDC 132
#define SMEM_BYTES (TILE_M * LDC * 4)   // C staging dominates (67584 B)

__global__ void __launch_bounds__(256, 2)
gemm_kernel(const float* __restrict__ x, const float* __restrict__ W,
            const float* __restrict__ bias, float* __restrict__ out) {
    int t = blockIdx.x;
    if (t >= g_ntiles) return;

    extern __shared__ float smem[];
    float* sA = smem;                     // 128 x LDA
    float* sB = smem + TILE_M * LDA;      // 32 x LDB
    float* sC = smem;                     // reused after mainloop

    const int e     = g_tile_expert[t];
    const int row0  = g_tile_row[t];
    const int valid = min(TILE_M, g_offsets[e + 1] - row0);
    const int n0    = blockIdx.y * TILE_N;

    const int tid    = threadIdx.x;
    const int warp   = tid >> 5;
    const int warp_m = warp >> 1;   // 0..3
    const int warp_n = warp & 1;    // 0..1

    // --- per-thread gather setup (A: 4 float4 per k-step) ---
    const int kc = tid & 7;               // float4 column within 32-wide k-tile
    int   tokrow[4];
    const float4* xrow[4];
    bool  rowok[4];
#pragma unroll
    for (int i = 0; i < 4; i++) {
        int m = (tid >> 3) + 32 * i;
        rowok[i]  = (m < valid);
        tokrow[i] = rowok[i] ? g_perm[row0 + m] : 0;
        xrow[i]   = (const float4*)(x + (size_t)tokrow[i] * DIN);
    }
    // --- B setup ---
    const int n4 = tid & 31;
    const int kkb = tid >> 5;             // + 8*i
    const float4* Wv = (const float4*)(W + (size_t)e * DIN * DOUT + n0);

    wmma::fragment<wmma::accumulator, 16, 16, 8, float> c[2][4];
#pragma unroll
    for (int i = 0; i < 2; i++)
#pragma unroll
        for (int j = 0; j < 4; j++) wmma::fill_fragment(c[i][j], 0.0f);

    for (int k0 = 0; k0 < DIN; k0 += TILE_K) {
        float4 ra[4], rb[4];
#pragma unroll
        for (int i = 0; i < 4; i++)
            ra[i] = rowok[i] ? xrow[i][(k0 >> 2) + kc]
                             : make_float4(0.f, 0.f, 0.f, 0.f);
#pragma unroll
        for (int i = 0; i < 4; i++)
            rb[i] = Wv[(size_t)(k0 + kkb + 8 * i) * (DOUT / 4) + n4];

        __syncthreads();   // previous compute finished reading smem
#pragma unroll
        for (int i = 0; i < 4; i++) {
            int m = (tid >> 3) + 32 * i;
            *(float4*)&sA[m * LDA + kc * 4] = ra[i];
        }
#pragma unroll
        for (int i = 0; i < 4; i++)
            *(float4*)&sB[(kkb + 8 * i) * LDB + n4 * 4] = rb[i];
        __syncthreads();

#pragma unroll
        for (int ks = 0; ks < 4; ks++) {
            wmma::fragment<wmma::matrix_a, 16, 16, 8, wmma::precision::tf32,
                           wmma::row_major> a[2];
            wmma::fragment<wmma::matrix_b, 16, 16, 8, wmma::precision::tf32,
                           wmma::row_major> bf[4];
#pragma unroll
            for (int i = 0; i < 2; i++) {
                wmma::load_matrix_sync(
                    a[i], &sA[(warp_m * 32 + i * 16) * LDA + ks * 8], LDA);
#pragma unroll
                for (int u = 0; u < a[i].num_elements; u++)
                    a[i].x[u] = wmma::__float_to_tf32(a[i].x[u]);
            }
#pragma unroll
            for (int j = 0; j < 4; j++) {
                wmma::load_matrix_sync(
                    bf[j], &sB[ks * 8 * LDB + warp_n * 64 + j * 16], LDB);
#pragma unroll
                for (int u = 0; u < bf[j].num_elements; u++)
                    bf[j].x[u] = wmma::__float_to_tf32(bf[j].x[u]);
            }
#pragma unroll
            for (int i = 0; i < 2; i++)
#pragma unroll
                for (int j = 0; j < 4; j++)
                    wmma::mma_sync(c[i][j], a[i], bf[j], c[i][j]);
        }
    }

    // --- epilogue: stage C in smem, then bias + scatter to gmem ---
    __syncthreads();
#pragma unroll
    for (int i = 0; i < 2; i++)
#pragma unroll
        for (int j = 0; j < 4; j++)
            wmma::store_matrix_sync(
                &sC[(warp_m * 32 + i * 16) * LDC + warp_n * 64 + j * 16],
                c[i][j], LDC, wmma::mem_row_major);
    __syncthreads();

    const float4* bv = (const float4*)(bias + (size_t)e * DOUT + n0);
    for (int f = tid; f < TILE_M * (TILE_N / 4); f += 256) {
        int m  = f >> 5;
        int c4 = f & 31;
        if (m < valid) {
            int token = g_perm[row0 + m];
            float4 v  = *(float4*)&sC[m * LDC + c4 * 4];
            float4 bb = bv[c4];
            v.x += bb.x; v.y += bb.y; v.z += bb.z; v.w += bb.w;
            *(float4*)&out[(size_t)token * DOUT + n0 + c4 * 4] = v;
        }
    }
}

// ---------------- launch ----------------------------------------------------
extern "C" void kernel_launch(void* const* d_in, const int* in_sizes, int n_in,
                              void* d_out, int out_size) {
    const float* x   = (const float*)d_in[0];
    const void*  idx = d_in[1];
    const float* W   = (const float*)d_in[2];
    const float* b   = (const float*)d_in[3];
    float* out = (float*)d_out;

    cudaFuncSetAttribute(gemm_kernel,
                         cudaFuncAttributeMaxDynamicSharedMemorySize,
                         SMEM_BYTES);

    k_init<<<1, 32>>>();
    k_detect<<<16, 256>>>((const unsigned*)idx);
    k_detect_fin<<<1, 1>>>();
    k_hist<<<BTOK / 256, 256>>>(idx);
    k_plan<<<1, 1>>>();
    k_scatter<<<BTOK / 256, 256>>>(idx);

    dim3 grid(MAX_TILES, DOUT / TILE_N);
    gemm_kernel<<<grid, 256, SMEM_BYTES>>>(x, W, b, out);
}

// round 3
// speedup vs baseline: 2.4737x; 2.4737x over previous
#include <cuda_runtime.h>
#include <cuda_fp16.h>
#include <mma.h>
#include <cstdint>

using namespace nvcuda;

#define LNUM   4
#define BTOK   16384
#define DIN    2048
#define DOUT   2048
#define TILE_M 128
#define TILE_N 128
#define TILE_K 32
#define NKT    (DIN / TILE_K)                 // 64
#define MAX_TILES (BTOK / TILE_M + LNUM)      // 132
#define NSTAGES 3

// ---------------- scratch (device globals; no allocation allowed) ----------
__device__ int      g_counts[LNUM];
__device__ int      g_offsets[LNUM + 1];
__device__ int      g_cursor[LNUM];
__device__ int      g_perm[BTOK];
__device__ int      g_tile_expert[MAX_TILES];
__device__ int      g_tile_row[MAX_TILES];
__device__ int      g_ntiles;
__device__ unsigned g_odd_or;
__device__ int      g_is64;
// fp16 operand buffers: x pre-permuted by expert (padded tail rows), W converted
__device__ __half   g_xh[(BTOK + TILE_M) * DIN];
__device__ __half   g_wh[LNUM * DIN * DOUT];

// ---------------- helpers ---------------------------------------------------
__device__ __forceinline__ uint32_t smem_u32(const void* p) {
    uint32_t a;
    asm("{ .reg .u64 t; cvta.to.shared.u64 t, %1; cvt.u32.u64 %0, t; }"
        : "=r"(a) : "l"(p));
    return a;
}
#define CP_ASYNC16(dst, src) \
    asm volatile("cp.async.cg.shared.global [%0], [%1], 16;" :: "r"(dst), "l"(src))
#define CP_COMMIT() asm volatile("cp.async.commit_group;" ::: "memory")
#define CP_WAIT(n)  asm volatile("cp.async.wait_group %0;" :: "n"(n) : "memory")

// ---------------- tiny prologue kernels -----------------------------------
__global__ void k_init() {
    int t = threadIdx.x;
    if (t < LNUM) { g_counts[t] = 0; g_cursor[t] = 0; }
    if (t == 0)   { g_odd_or = 0u; }
}
// int64 vs int32 layer_idx detection (odd words all-zero => int64)
__global__ void k_detect(const unsigned* idx_words) {
    unsigned acc = 0;
    for (int j = 1 + 2 * (blockIdx.x * blockDim.x + threadIdx.x); j < BTOK;
         j += 2 * gridDim.x * blockDim.x)
        acc |= idx_words[j];
    if (acc) atomicOr(&g_odd_or, acc);
}
__global__ void k_detect_fin() { g_is64 = (g_odd_or == 0u) ? 1 : 0; }

__device__ __forceinline__ int read_expert(const void* idx, int j) {
    if (g_is64) return (int)((const long long*)idx)[j];
    return ((const int*)idx)[j];
}
__global__ void k_hist(const void* idx) {
    int j = blockIdx.x * blockDim.x + threadIdx.x;
    if (j < BTOK) atomicAdd(&g_counts[read_expert(idx, j)], 1);
}
__global__ void k_plan() {
    g_offsets[0] = 0;
    for (int e = 0; e < LNUM; e++) g_offsets[e + 1] = g_offsets[e] + g_counts[e];
    int nt = 0;
    for (int e = 0; e < LNUM; e++)
        for (int r = g_offsets[e]; r < g_offsets[e + 1]; r += TILE_M) {
            g_tile_expert[nt] = e; g_tile_row[nt] = r; nt++;
        }
    g_ntiles = nt;
}
__global__ void k_scatter(const void* idx) {
    int j = blockIdx.x * blockDim.x + threadIdx.x;
    if (j < BTOK) {
        int e = read_expert(idx, j);
        int p = atomicAdd(&g_cursor[e], 1);
        g_perm[g_offsets[e] + p] = j;
    }
}
// W fp32 -> fp16 (8 elems / thread)
__global__ void k_convert_w(const float* __restrict__ W) {
    size_t i = ((size_t)blockIdx.x * blockDim.x + threadIdx.x) * 8;
    float4 a = *(const float4*)(W + i);
    float4 b = *(const float4*)(W + i + 4);
    __half2 h[4];
    h[0] = __floats2half2_rn(a.x, a.y);
    h[1] = __floats2half2_rn(a.z, a.w);
    h[2] = __floats2half2_rn(b.x, b.y);
    h[3] = __floats2half2_rn(b.z, b.w);
    *(uint4*)(g_wh + i) = *(uint4*)h;
}
// x fp32 -> fp16, permuted: block p copies token g_perm[p] into row p
__global__ void k_convert_x(const float* __restrict__ x) {
    int p = blockIdx.x;
    int j = g_perm[p];
    const float* src = x + (size_t)j * DIN + threadIdx.x * 8;
    __half* dst = g_xh + (size_t)p * DIN + threadIdx.x * 8;
    float4 a = *(const float4*)src;
    float4 b = *(const float4*)(src + 4);
    __half2 h[4];
    h[0] = __floats2half2_rn(a.x, a.y);
    h[1] = __floats2half2_rn(a.z, a.w);
    h[2] = __floats2half2_rn(b.x, b.y);
    h[3] = __floats2half2_rn(b.z, b.w);
    *(uint4*)dst = *(uint4*)h;
}

// ---------------- GEMM: fp16 wmma + cp.async 3-stage pipeline ---------------
// A smem: [128][40] half (80B rows), B smem: [32][136] half (272B rows).
#define A_LD   40
#define B_LD   136
#define A_BYTES (TILE_M * A_LD * 2)           // 10240
#define B_BYTES (TILE_K * B_LD * 2)           // 8704
#define STG_BYTES (A_BYTES + B_BYTES)         // 18944
#define C_LD   132
#define C_BYTES (TILE_M * C_LD * 4)           // 67584
#define SMEM_TOTAL (C_BYTES)                  // > 3*STG_BYTES (56832)

__global__ void __launch_bounds__(256, 2)
gemm_kernel(const float* __restrict__ bias, float* __restrict__ out) {
    const int t = blockIdx.x;
    if (t >= g_ntiles) return;

    extern __shared__ char smem[];
    const uint32_t sb = smem_u32(smem);
    const int tid  = threadIdx.x;
    const int wid  = tid >> 5;
    const int warp_m = wid & 3;               // 4 warps in M
    const int warp_n = wid >> 2;              // 2 warps in N

    const int e      = g_tile_expert[t];
    const int row0   = g_tile_row[t];
    const int endRow = g_offsets[e + 1];
    const int n0     = blockIdx.y * TILE_N;

    // per-thread cp.async plumbing
    const int arow = tid >> 1;                // 2 threads/row (2 x 16B = 32B/row? no:)
    // A: 128 rows x 64B -> 512 x 16B slots; thread covers slot tid and tid+256
    // slot s: row = s>>2, c16 = s&3
    const __half* xbase = g_xh + (size_t)row0 * DIN;
    const __half* wbase = g_wh + (size_t)e * DIN * DOUT + n0;
    (void)arow;

    auto issue_stage = [&](int buf, int k0) {
#pragma unroll
        for (int pass = 0; pass < 2; pass++) {
            int s = tid + pass * 256;
            int row = s >> 2, c16 = s & 3;
            const void* src = xbase + (size_t)row * DIN + k0 + c16 * 8;
            uint32_t dst = sb + buf * STG_BYTES + row * (A_LD * 2) + c16 * 16;
            CP_ASYNC16(dst, src);
        }
#pragma unroll
        for (int pass = 0; pass < 2; pass++) {
            int s = tid + pass * 256;
            int k = s >> 4, n16 = s & 15;
            const void* src = wbase + (size_t)(k0 + k) * DOUT + n16 * 8;
            uint32_t dst = sb + buf * STG_BYTES + A_BYTES + k * (B_LD * 2) + n16 * 16;
            CP_ASYNC16(dst, src);
        }
    };

    wmma::fragment<wmma::accumulator, 16, 16, 16, float> acc[2][4];
#pragma unroll
    for (int i = 0; i < 2; i++)
#pragma unroll
        for (int j = 0; j < 4; j++) wmma::fill_fragment(acc[i][j], 0.0f);

    issue_stage(0, 0);  CP_COMMIT();
    issue_stage(1, 32); CP_COMMIT();

    for (int i = 0; i < NKT; i++) {
        const int buf = i % NSTAGES;
        CP_WAIT(1);
        __syncthreads();

        const __half* sA = (const __half*)(smem + buf * STG_BYTES);
        const __half* sB = (const __half*)(smem + buf * STG_BYTES + A_BYTES);
#pragma unroll
        for (int ks = 0; ks < 2; ks++) {
            wmma::fragment<wmma::matrix_a, 16, 16, 16, __half, wmma::row_major> af[2];
            wmma::fragment<wmma::matrix_b, 16, 16, 16, __half, wmma::row_major> bf[4];
#pragma unroll
            for (int m = 0; m < 2; m++)
                wmma::load_matrix_sync(af[m],
                    sA + (warp_m * 32 + m * 16) * A_LD + ks * 16, A_LD);
#pragma unroll
            for (int n = 0; n < 4; n++)
                wmma::load_matrix_sync(bf[n],
                    sB + (ks * 16) * B_LD + warp_n * 64 + n * 16, B_LD);
#pragma unroll
            for (int m = 0; m < 2; m++)
#pragma unroll
                for (int n = 0; n < 4; n++)
                    wmma::mma_sync(acc[m][n], af[m], bf[n], acc[m][n]);
        }
        __syncthreads();

        if (i + 2 < NKT) issue_stage((i + 2) % NSTAGES, (i + 2) * TILE_K);
        CP_COMMIT();
    }

    // ---- epilogue: stage C in smem, bias + scatter rows by g_perm ----
    float* sC = (float*)smem;
#pragma unroll
    for (int m = 0; m < 2; m++)
#pragma unroll
        for (int n = 0; n < 4; n++)
            wmma::store_matrix_sync(
                sC + (warp_m * 32 + m * 16) * C_LD + warp_n * 64 + n * 16,
                acc[m][n], C_LD, wmma::mem_row_major);
    __syncthreads();

    const float4* bv = (const float4*)(bias + (size_t)e * DOUT + n0);
    for (int f = tid; f < TILE_M * (TILE_N / 4); f += 256) {
        int m  = f >> 5;
        int c4 = f & 31;
        if (row0 + m < endRow) {
            int token = g_perm[row0 + m];
            float4 v  = *(float4*)&sC[m * C_LD + c4 * 4];
            float4 bb = bv[c4];
            v.x += bb.x; v.y += bb.y; v.z += bb.z; v.w += bb.w;
            *(float4*)&out[(size_t)token * DOUT + n0 + c4 * 4] = v;
        }
    }
}

// ---------------- launch ----------------------------------------------------
extern "C" void kernel_launch(void* const* d_in, const int* in_sizes, int n_in,
                              void* d_out, int out_size) {
    const float* x   = (const float*)d_in[0];
    const void*  idx = d_in[1];
    const float* W   = (const float*)d_in[2];
    const float* b   = (const float*)d_in[3];
    float* out = (float*)d_out;

    cudaFuncSetAttribute(gemm_kernel,
                         cudaFuncAttributeMaxDynamicSharedMemorySize, SMEM_TOTAL);

    k_init<<<1, 32>>>();
    k_detect<<<16, 256>>>((const unsigned*)idx);
    k_detect_fin<<<1, 1>>>();
    k_hist<<<BTOK / 256, 256>>>(idx);
    k_plan<<<1, 1>>>();
    k_scatter<<<BTOK / 256, 256>>>(idx);
    k_convert_w<<<(LNUM * DIN * DOUT) / (256 * 8), 256>>>(W);
    k_convert_x<<<BTOK, 256>>>(x);

    dim3 grid(MAX_TILES, DOUT / TILE_N);
    gemm_kernel<<<grid, 256, SMEM_TOTAL>>>(b, out);
}

// round 4
// speedup vs baseline: 5.2108x; 2.1065x over previous
#include <cuda_runtime.h>
#include <cuda_fp16.h>
#include <cstdint>

#define LNUM   4
#define BTOK   16384
#define DIN    2048
#define DOUT   2048
#define TILE_M 128
#define TILE_N 128
#define TILE_K 64
#define NKT    (DIN / TILE_K)                 // 32
#define MAX_TILES (BTOK / TILE_M + LNUM)      // 132
#define NSTAGES 3

// ---------------- scratch (device globals; no allocation allowed) ----------
__device__ int    g_offsets[LNUM + 1];
__device__ int    g_perm[BTOK];
__device__ int    g_tile_expert[MAX_TILES];
__device__ int    g_tile_row[MAX_TILES];
__device__ int    g_ntiles;
__device__ __half g_xh[(BTOK + TILE_M) * DIN];   // pre-permuted fp16 x (+pad)
__device__ __half g_wh[LNUM * DIN * DOUT];       // fp16 W

// ---------------- helpers ---------------------------------------------------
__device__ __forceinline__ uint32_t smem_u32(const void* p) {
    uint32_t a;
    asm("{ .reg .u64 t; cvta.to.shared.u64 t, %1; cvt.u32.u64 %0, t; }"
        : "=r"(a) : "l"(p));
    return a;
}
#define CP_ASYNC16(dst, src) \
    asm volatile("cp.async.cg.shared.global [%0], [%1], 16;" :: "r"(dst), "l"(src))
#define CP_COMMIT() asm volatile("cp.async.commit_group;" ::: "memory")
#define CP_WAIT(n)  asm volatile("cp.async.wait_group %0;" :: "n"(n) : "memory")

#define LDSM_X4(r0, r1, r2, r3, a) \
    asm volatile("ldmatrix.sync.aligned.m8n8.x4.shared.b16 {%0,%1,%2,%3}, [%4];" \
                 : "=r"(r0), "=r"(r1), "=r"(r2), "=r"(r3) : "r"(a))
#define LDSM_X4T(r0, r1, r2, r3, a) \
    asm volatile("ldmatrix.sync.aligned.m8n8.x4.trans.shared.b16 {%0,%1,%2,%3}, [%4];" \
                 : "=r"(r0), "=r"(r1), "=r"(r2), "=r"(r3) : "r"(a))
#define MMA16816(d, a, b0, b1)                                               \
    asm volatile("mma.sync.aligned.m16n8k16.row.col.f32.f16.f16.f32 "        \
        "{%0,%1,%2,%3}, {%4,%5,%6,%7}, {%8,%9}, {%0,%1,%2,%3};"              \
        : "+f"((d)[0]), "+f"((d)[1]), "+f"((d)[2]), "+f"((d)[3])             \
        : "r"((a)[0]), "r"((a)[1]), "r"((a)[2]), "r"((a)[3]), "r"(b0), "r"(b1))

// ---------------- fused planning kernel (single block) ----------------------
__global__ void k_setup(const unsigned* idx_words) {
    __shared__ int      s_cnt[LNUM], s_cur[LNUM], s_off[LNUM + 1];
    __shared__ unsigned s_odd;
    __shared__ int      s_is64;
    const int t = threadIdx.x;   // 1024 threads

    if (t < LNUM) { s_cnt[t] = 0; s_cur[t] = 0; }
    if (t == 0) s_odd = 0u;
    __syncthreads();

    // int64 vs int32 detect: int64 little-endian high words (odd u32) all zero
    unsigned acc = 0;
    for (int j = 1 + 2 * t; j < BTOK; j += 2048) acc |= idx_words[j];
    if (acc) atomicOr(&s_odd, acc);
    __syncthreads();
    if (t == 0) s_is64 = (s_odd == 0u);
    __syncthreads();
    const int is64 = s_is64;

    for (int j = t; j < BTOK; j += 1024) {
        int e = is64 ? (int)((const long long*)idx_words)[j]
                     : ((const int*)idx_words)[j];
        atomicAdd(&s_cnt[e], 1);
    }
    __syncthreads();

    if (t == 0) {
        s_off[0] = 0;
        for (int e = 0; e < LNUM; e++) s_off[e + 1] = s_off[e] + s_cnt[e];
        for (int e = 0; e <= LNUM; e++) g_offsets[e] = s_off[e];
        int nt = 0;
        for (int e = 0; e < LNUM; e++)
            for (int r = s_off[e]; r < s_off[e + 1]; r += TILE_M) {
                g_tile_expert[nt] = e; g_tile_row[nt] = r; nt++;
            }
        g_ntiles = nt;
    }
    __syncthreads();

    for (int j = t; j < BTOK; j += 1024) {
        int e = is64 ? (int)((const long long*)idx_words)[j]
                     : ((const int*)idx_words)[j];
        int p = atomicAdd(&s_cur[e], 1);
        g_perm[s_off[e] + p] = j;
    }
}

// ---------------- fp32 -> fp16 converters -----------------------------------
__global__ void k_convert_w(const float* __restrict__ W) {
    size_t i = ((size_t)blockIdx.x * blockDim.x + threadIdx.x) * 8;
    float4 a = *(const float4*)(W + i);
    float4 b = *(const float4*)(W + i + 4);
    __half2 h[4];
    h[0] = __floats2half2_rn(a.x, a.y);
    h[1] = __floats2half2_rn(a.z, a.w);
    h[2] = __floats2half2_rn(b.x, b.y);
    h[3] = __floats2half2_rn(b.z, b.w);
    *(uint4*)(g_wh + i) = *(uint4*)h;
}
__global__ void k_convert_x(const float* __restrict__ x) {
    int p = blockIdx.x;
    int j = g_perm[p];
    const float* src = x + (size_t)j * DIN + threadIdx.x * 8;
    __half* dst = g_xh + (size_t)p * DIN + threadIdx.x * 8;
    float4 a = *(const float4*)src;
    float4 b = *(const float4*)(src + 4);
    __half2 h[4];
    h[0] = __floats2half2_rn(a.x, a.y);
    h[1] = __floats2half2_rn(a.z, a.w);
    h[2] = __floats2half2_rn(b.x, b.y);
    h[3] = __floats2half2_rn(b.z, b.w);
    *(uint4*)dst = *(uint4*)h;
}

// ---------------- GEMM: mma.sync fp16, K-tile 64, 3-stage cp.async ----------
// A stage: 128 rows x 128B (64 halves), XOR-swizzled 16B chunks.
// B stage: 64 k-rows x 256B (128 halves), XOR-swizzled within 128B halves.
#define A_STG   16384
#define B_STG   16384
#define STG     (A_STG + B_STG)               // 32768
#define C_LD    132
#define SMEM_TOTAL (NSTAGES * STG)            // 98304 (> C staging 67584)

__global__ void __launch_bounds__(256, 2)
gemm_kernel(const float* __restrict__ bias, float* __restrict__ out) {
    const int t = blockIdx.x;
    if (t >= g_ntiles) return;

    extern __shared__ char smem[];
    const uint32_t sb = smem_u32(smem);
    const int tid    = threadIdx.x;
    const int lane   = tid & 31;
    const int wid    = tid >> 5;
    const int warp_m = wid & 3;               // 4 warps in M
    const int warp_n = wid >> 2;              // 2 warps in N

    const int e      = g_tile_expert[t];
    const int row0   = g_tile_row[t];
    const int endRow = g_offsets[e + 1];
    const int n0     = blockIdx.y * TILE_N;

    // ---- cp.async per-thread plumbing (4 A + 4 B 16B copies per stage) ----
    const __half* asrc[4];
    const __half* bsrc[4];
    uint32_t adst[4], bdst[4];
    {
        const __half* xbase = g_xh + (size_t)row0 * DIN;
        const __half* wbase = g_wh + (size_t)e * DIN * DOUT + n0;
#pragma unroll
        for (int p = 0; p < 4; p++) {
            int s = tid + p * 256;            // A slot: r = s>>3, c = s&7
            int r = s >> 3, c = s & 7;
            asrc[p] = xbase + (size_t)r * DIN + c * 8;
            adst[p] = (uint32_t)(r * 128 + ((c ^ (r & 7)) << 4));
            int kr = s >> 4, cb = s & 15;     // B slot
            bsrc[p] = wbase + (size_t)kr * DOUT + cb * 8;
            bdst[p] = (uint32_t)(A_STG + kr * 256 +
                                 ((((cb & 7) ^ (kr & 7)) | (cb & 8)) << 4));
        }
    }
    auto issue_stage = [&](int buf) {
        uint32_t base = sb + buf * STG;
#pragma unroll
        for (int p = 0; p < 4; p++) CP_ASYNC16(base + adst[p], asrc[p]);
#pragma unroll
        for (int p = 0; p < 4; p++) CP_ASYNC16(base + bdst[p], bsrc[p]);
#pragma unroll
        for (int p = 0; p < 4; p++) { asrc[p] += TILE_K; bsrc[p] += (size_t)TILE_K * DOUT; }
    };

    // ---- ldmatrix per-lane address components ----
    const int l15 = lane & 15, lhi = lane >> 4, l7 = lane & 7;
    // A: row = warp_m*32 + m*16 + l15; chunk = 2s + lhi, swz ^ l7
    uint32_t aRow[2];
#pragma unroll
    for (int m = 0; m < 2; m++)
        aRow[m] = (uint32_t)((warp_m * 32 + m * 16 + l15) * 128);
    // B: krow = s*16 + l15; chunk' = ((2f + lhi) ^ l7) | warp_n*8
    const uint32_t bRowOff = (uint32_t)(A_STG + l15 * 256);
    uint32_t bChunk[4];
#pragma unroll
    for (int f = 0; f < 4; f++)
        bChunk[f] = (uint32_t)(((((2 * f + lhi) ^ l7)) | (warp_n * 8)) << 4);
    uint32_t aChunk[4][2];
#pragma unroll
    for (int s = 0; s < 4; s++)
#pragma unroll
        for (int m = 0; m < 2; m++)
            aChunk[s][m] = aRow[m] + (uint32_t)(((2 * s + lhi) ^ l7) << 4);

    float acc[2][8][4];
#pragma unroll
    for (int m = 0; m < 2; m++)
#pragma unroll
        for (int n = 0; n < 8; n++)
#pragma unroll
            for (int q = 0; q < 4; q++) acc[m][n][q] = 0.0f;

    issue_stage(0); CP_COMMIT();
    issue_stage(1); CP_COMMIT();

    for (int i = 0; i < NKT; i++) {
        const int buf = i % NSTAGES;
        CP_WAIT(1);
        __syncthreads();
        const uint32_t base = sb + buf * STG;

#pragma unroll
        for (int s = 0; s < 4; s++) {
            uint32_t a[2][4];
#pragma unroll
            for (int m = 0; m < 2; m++)
                LDSM_X4(a[m][0], a[m][1], a[m][2], a[m][3], base + aChunk[s][m]);
            const uint32_t brow = base + bRowOff + s * 4096;
#pragma unroll
            for (int f = 0; f < 4; f++) {
                uint32_t b0, b1, b2, b3;
                LDSM_X4T(b0, b1, b2, b3, brow + bChunk[f]);
                MMA16816(acc[0][2 * f],     a[0], b0, b1);
                MMA16816(acc[1][2 * f],     a[1], b0, b1);
                MMA16816(acc[0][2 * f + 1], a[0], b2, b3);
                MMA16816(acc[1][2 * f + 1], a[1], b2, b3);
            }
        }
        if (i + 2 < NKT) issue_stage((i + 2) % NSTAGES);
        CP_COMMIT();
    }

    // ---- epilogue: stage C in smem (reuses stage mem), bias + scatter ----
    __syncthreads();
    float* sC = (float*)smem;
#pragma unroll
    for (int m = 0; m < 2; m++) {
        int rbase = warp_m * 32 + m * 16 + (lane >> 2);
#pragma unroll
        for (int n = 0; n < 8; n++) {
            int col = warp_n * 64 + n * 8 + (lane & 3) * 2;
            *(float2*)&sC[rbase * C_LD + col] =
                make_float2(acc[m][n][0], acc[m][n][1]);
            *(float2*)&sC[(rbase + 8) * C_LD + col] =
                make_float2(acc[m][n][2], acc[m][n][3]);
        }
    }
    __syncthreads();

    const float4* bv = (const float4*)(bias + (size_t)e * DOUT + n0);
    for (int f = tid; f < TILE_M * (TILE_N / 4); f += 256) {
        int m  = f >> 5;
        int c4 = f & 31;
        if (row0 + m < endRow) {
            int token = g_perm[row0 + m];
            float4 v  = *(float4*)&sC[m * C_LD + c4 * 4];
            float4 bb = bv[c4];
            v.x += bb.x; v.y += bb.y; v.z += bb.z; v.w += bb.w;
            *(float4*)&out[(size_t)token * DOUT + n0 + c4 * 4] = v;
        }
    }
}

// ---------------- launch ----------------------------------------------------
extern "C" void kernel_launch(void* const* d_in, const int* in_sizes, int n_in,
                              void* d_out, int out_size) {
    const float* x   = (const float*)d_in[0];
    const void*  idx = d_in[1];
    const float* W   = (const float*)d_in[2];
    const float* b   = (const float*)d_in[3];
    float* out = (float*)d_out;

    cudaFuncSetAttribute(gemm_kernel,
                         cudaFuncAttributeMaxDynamicSharedMemorySize, SMEM_TOTAL);

    k_setup<<<1, 1024>>>((const unsigned*)idx);                     // launch 1
    k_convert_w<<<(LNUM * DIN * DOUT) / (256 * 8), 256>>>(W);       // launch 2
    k_convert_x<<<BTOK, 256>>>(x);                                  // launch 3
    dim3 grid(MAX_TILES, DOUT / TILE_N);
    gemm_kernel<<<grid, 256, SMEM_TOTAL>>>(b, out);                 // launch 4
}

// round 5
// speedup vs baseline: 5.2507x; 1.0076x over previous
#include <cuda_runtime.h>
#include <cuda_fp16.h>
#include <cstdint>

#define LNUM   4
#define BTOK   16384
#define DIN    2048
#define DOUT   2048
#define TILE_M 128
#define TILE_N 128
#define TILE_K 64
#define NKT    (DIN / TILE_K)                 // 32
#define MAX_TILES (BTOK / TILE_M + LNUM)      // 132
#define NSTAGES 3

// ---------------- scratch (device globals; no allocation allowed) ----------
__device__ int    g_offsets[LNUM + 1];
__device__ int    g_perm[BTOK];
__device__ int    g_tile_expert[MAX_TILES];
__device__ int    g_tile_row[MAX_TILES];
__device__ int    g_ntiles;
__device__ __half g_xh[(BTOK + TILE_M) * DIN];   // pre-permuted fp16 x (+pad)
__device__ __half g_wh[LNUM * DIN * DOUT];       // fp16 W

// ---------------- helpers ---------------------------------------------------
__device__ __forceinline__ uint32_t smem_u32(const void* p) {
    uint32_t a;
    asm("{ .reg .u64 t; cvta.to.shared.u64 t, %1; cvt.u32.u64 %0, t; }"
        : "=r"(a) : "l"(p));
    return a;
}
#define CP_ASYNC16(dst, src) \
    asm volatile("cp.async.cg.shared.global [%0], [%1], 16;" :: "r"(dst), "l"(src))
#define CP_COMMIT() asm volatile("cp.async.commit_group;" ::: "memory")
#define CP_WAIT(n)  asm volatile("cp.async.wait_group %0;" :: "n"(n) : "memory")

#define LDSM_X4(r0, r1, r2, r3, a) \
    asm volatile("ldmatrix.sync.aligned.m8n8.x4.shared.b16 {%0,%1,%2,%3}, [%4];" \
                 : "=r"(r0), "=r"(r1), "=r"(r2), "=r"(r3) : "r"(a))
#define LDSM_X4T(r0, r1, r2, r3, a) \
    asm volatile("ldmatrix.sync.aligned.m8n8.x4.trans.shared.b16 {%0,%1,%2,%3}, [%4];" \
                 : "=r"(r0), "=r"(r1), "=r"(r2), "=r"(r3) : "r"(a))
#define MMA16816(d, a, b0, b1)                                               \
    asm volatile("mma.sync.aligned.m16n8k16.row.col.f32.f16.f16.f32 "        \
        "{%0,%1,%2,%3}, {%4,%5,%6,%7}, {%8,%9}, {%0,%1,%2,%3};"              \
        : "+f"((d)[0]), "+f"((d)[1]), "+f"((d)[2]), "+f"((d)[3])             \
        : "r"((a)[0]), "r"((a)[1]), "r"((a)[2]), "r"((a)[3]), "r"(b0), "r"(b1))

// ---------------- fused planning kernel (single block) ----------------------
__global__ void k_setup(const unsigned* idx_words) {
    __shared__ int      s_cnt[LNUM], s_cur[LNUM], s_off[LNUM + 1];
    __shared__ unsigned s_odd;
    __shared__ int      s_is64;
    const int t = threadIdx.x;   // 1024 threads

    if (t < LNUM) { s_cnt[t] = 0; s_cur[t] = 0; }
    if (t == 0) s_odd = 0u;
    __syncthreads();

    // int64 vs int32 detect: int64 little-endian high words (odd u32) all zero
    unsigned acc = 0;
    for (int j = 1 + 2 * t; j < BTOK; j += 2048) acc |= idx_words[j];
    if (acc) atomicOr(&s_odd, acc);
    __syncthreads();
    if (t == 0) s_is64 = (s_odd == 0u);
    __syncthreads();
    const int is64 = s_is64;

    for (int j = t; j < BTOK; j += 1024) {
        int e = is64 ? (int)((const long long*)idx_words)[j]
                     : ((const int*)idx_words)[j];
        atomicAdd(&s_cnt[e], 1);
    }
    __syncthreads();

    if (t == 0) {
        s_off[0] = 0;
        for (int e = 0; e < LNUM; e++) s_off[e + 1] = s_off[e] + s_cnt[e];
        for (int e = 0; e <= LNUM; e++) g_offsets[e] = s_off[e];
        int nt = 0;
        for (int e = 0; e < LNUM; e++)
            for (int r = s_off[e]; r < s_off[e + 1]; r += TILE_M) {
                g_tile_expert[nt] = e; g_tile_row[nt] = r; nt++;
            }
        g_ntiles = nt;
    }
    __syncthreads();

    for (int j = t; j < BTOK; j += 1024) {
        int e = is64 ? (int)((const long long*)idx_words)[j]
                     : ((const int*)idx_words)[j];
        int p = atomicAdd(&s_cur[e], 1);
        g_perm[s_off[e] + p] = j;
    }
}

// ---------------- fused fp32 -> fp16 converter ------------------------------
// blocks [0, 8192): W chunks (2048 elems each).  blocks [8192, 8192+BTOK):
// permuted x rows (2048 elems each).
#define W_BLOCKS ((LNUM * DIN * DOUT) / 2048)    // 8192
__global__ void k_convert(const float* __restrict__ W, const float* __restrict__ x) {
    const int b = blockIdx.x;
    const float* src;
    __half* dst;
    if (b < W_BLOCKS) {
        size_t i = (size_t)b * 2048 + threadIdx.x * 8;
        src = W + i;
        dst = g_wh + i;
    } else {
        int p = b - W_BLOCKS;
        int j = g_perm[p];
        src = x + (size_t)j * DIN + threadIdx.x * 8;
        dst = g_xh + (size_t)p * DIN + threadIdx.x * 8;
    }
    float4 a = *(const float4*)src;
    float4 c = *(const float4*)(src + 4);
    __half2 h[4];
    h[0] = __floats2half2_rn(a.x, a.y);
    h[1] = __floats2half2_rn(a.z, a.w);
    h[2] = __floats2half2_rn(c.x, c.y);
    h[3] = __floats2half2_rn(c.z, c.w);
    *(uint4*)dst = *(uint4*)h;
}

// ---------------- GEMM: mma.sync fp16, K-tile 64, 3-stage cp.async ----------
#define A_STG   16384
#define B_STG   16384
#define STG     (A_STG + B_STG)               // 32768
#define C_LD    132
#define SMEM_TOTAL (NSTAGES * STG)            // 98304 (> C staging 67584)

__global__ void __launch_bounds__(256, 2)
gemm_kernel(const float* __restrict__ bias, float* __restrict__ out) {
    const int t = blockIdx.x;
    if (t >= g_ntiles) return;

    extern __shared__ char smem[];
    const uint32_t sb = smem_u32(smem);
    const int tid    = threadIdx.x;
    const int lane   = tid & 31;
    const int wid    = tid >> 5;
    const int warp_m = wid & 3;               // 4 warps in M
    const int warp_n = wid >> 2;              // 2 warps in N

    const int e      = g_tile_expert[t];
    const int row0   = g_tile_row[t];
    const int endRow = g_offsets[e + 1];
    const int n0     = blockIdx.y * TILE_N;

    // ---- cp.async per-thread plumbing (4 A + 4 B 16B copies per stage) ----
    const __half* asrc[4];
    const __half* bsrc[4];
    uint32_t adst[4], bdst[4];
    {
        const __half* xbase = g_xh + (size_t)row0 * DIN;
        const __half* wbase = g_wh + (size_t)e * DIN * DOUT + n0;
#pragma unroll
        for (int p = 0; p < 4; p++) {
            int s = tid + p * 256;            // A slot: r = s>>3, c = s&7
            int r = s >> 3, c = s & 7;
            asrc[p] = xbase + (size_t)r * DIN + c * 8;
            adst[p] = (uint32_t)(r * 128 + ((c ^ (r & 7)) << 4));
            int kr = s >> 4, cb = s & 15;     // B slot
            bsrc[p] = wbase + (size_t)kr * DOUT + cb * 8;
            bdst[p] = (uint32_t)(A_STG + kr * 256 +
                                 ((((cb & 7) ^ (kr & 7)) | (cb & 8)) << 4));
        }
    }
    auto issue_stage = [&](int buf) {
        uint32_t base = sb + buf * STG;
#pragma unroll
        for (int p = 0; p < 4; p++) CP_ASYNC16(base + adst[p], asrc[p]);
#pragma unroll
        for (int p = 0; p < 4; p++) CP_ASYNC16(base + bdst[p], bsrc[p]);
#pragma unroll
        for (int p = 0; p < 4; p++) { asrc[p] += TILE_K; bsrc[p] += (size_t)TILE_K * DOUT; }
    };

    // ---- ldmatrix per-lane address components ----
    const int l15 = lane & 15, lhi = lane >> 4, l7 = lane & 7;
    uint32_t aRow[2];
#pragma unroll
    for (int m = 0; m < 2; m++)
        aRow[m] = (uint32_t)((warp_m * 32 + m * 16 + l15) * 128);
    const uint32_t bRowOff = (uint32_t)(A_STG + l15 * 256);
    uint32_t bChunk[4];
#pragma unroll
    for (int f = 0; f < 4; f++)
        bChunk[f] = (uint32_t)(((((2 * f + lhi) ^ l7)) | (warp_n * 8)) << 4);
    uint32_t aChunk[4][2];
#pragma unroll
    for (int s = 0; s < 4; s++)
#pragma unroll
        for (int m = 0; m < 2; m++)
            aChunk[s][m] = aRow[m] + (uint32_t)(((2 * s + lhi) ^ l7) << 4);

    float acc[2][8][4];
#pragma unroll
    for (int m = 0; m < 2; m++)
#pragma unroll
        for (int n = 0; n < 8; n++)
#pragma unroll
            for (int q = 0; q < 4; q++) acc[m][n][q] = 0.0f;

    issue_stage(0); CP_COMMIT();
    issue_stage(1); CP_COMMIT();

#pragma unroll 3
    for (int i = 0; i < NKT; i++) {
        const int buf = i % NSTAGES;
        CP_WAIT(1);
        __syncthreads();

        // issue next stage FIRST: overlaps loads with the whole MMA body.
        // buffer (i+2)%3 == (i-1)%3; all warps finished reading it before
        // the barrier above.
        if (i + 2 < NKT) issue_stage((i + 2) % NSTAGES);
        CP_COMMIT();

        const uint32_t base = sb + buf * STG;
#pragma unroll
        for (int s = 0; s < 4; s++) {
            uint32_t a[2][4];
#pragma unroll
            for (int m = 0; m < 2; m++)
                LDSM_X4(a[m][0], a[m][1], a[m][2], a[m][3], base + aChunk[s][m]);
            const uint32_t brow = base + bRowOff + s * 4096;
#pragma unroll
            for (int f = 0; f < 4; f++) {
                uint32_t b0, b1, b2, b3;
                LDSM_X4T(b0, b1, b2, b3, brow + bChunk[f]);
                MMA16816(acc[0][2 * f],     a[0], b0, b1);
                MMA16816(acc[1][2 * f],     a[1], b0, b1);
                MMA16816(acc[0][2 * f + 1], a[0], b2, b3);
                MMA16816(acc[1][2 * f + 1], a[1], b2, b3);
            }
        }
    }

    // ---- epilogue: stage C in smem (reuses stage mem), bias + scatter ----
    CP_WAIT(0);
    __syncthreads();
    float* sC = (float*)smem;
#pragma unroll
    for (int m = 0; m < 2; m++) {
        int rbase = warp_m * 32 + m * 16 + (lane >> 2);
#pragma unroll
        for (int n = 0; n < 8; n++) {
            int col = warp_n * 64 + n * 8 + (lane & 3) * 2;
            *(float2*)&sC[rbase * C_LD + col] =
                make_float2(acc[m][n][0], acc[m][n][1]);
            *(float2*)&sC[(rbase + 8) * C_LD + col] =
                make_float2(acc[m][n][2], acc[m][n][3]);
        }
    }
    __syncthreads();

    const float4* bv = (const float4*)(bias + (size_t)e * DOUT + n0);
    for (int f = tid; f < TILE_M * (TILE_N / 4); f += 256) {
        int m  = f >> 5;
        int c4 = f & 31;
        if (row0 + m < endRow) {
            int token = g_perm[row0 + m];
            float4 v  = *(float4*)&sC[m * C_LD + c4 * 4];
            float4 bb = bv[c4];
            v.x += bb.x; v.y += bb.y; v.z += bb.z; v.w += bb.w;
            *(float4*)&out[(size_t)token * DOUT + n0 + c4 * 4] = v;
        }
    }
}

// ---------------- launch ----------------------------------------------------
extern "C" void kernel_launch(void* const* d_in, const int* in_sizes, int n_in,
                              void* d_out, int out_size) {
    const float* x   = (const float*)d_in[0];
    const void*  idx = d_in[1];
    const float* W   = (const float*)d_in[2];
    const float* b   = (const float*)d_in[3];
    float* out = (float*)d_out;

    cudaFuncSetAttribute(gemm_kernel,
                         cudaFuncAttributeMaxDynamicSharedMemorySize, SMEM_TOTAL);

    k_setup<<<1, 1024>>>((const unsigned*)idx);                 // launch 1
    k_convert<<<W_BLOCKS + BTOK, 256>>>(W, x);                  // launch 2
    dim3 grid(MAX_TILES, DOUT / TILE_N);
    gemm_kernel<<<grid, 256, SMEM_TOTAL>>>(b, out);             // launch 3
}

// round 6
// speedup vs baseline: 5.5469x; 1.0564x over previous
#include <cuda_runtime.h>
#include <cuda_fp16.h>
#include <cstdint>

#define LNUM   4
#define BTOK   16384
#define DIN    2048
#define DOUT   2048
#define TILE_M 128
#define TILE_N 128
#define TILE_K 64
#define NKT    (DIN / TILE_K)                 // 32
#define MAX_TILES (BTOK / TILE_M + LNUM)      // 132
#define NSTAGES 3

// ---------------- scratch (device globals; no allocation allowed) ----------
__device__ int    g_offsets[LNUM + 1];
__device__ int    g_perm[BTOK];
__device__ int    g_tile_expert[MAX_TILES];
__device__ int    g_tile_row[MAX_TILES];
__device__ int    g_ntiles;
__device__ __half g_xh[(BTOK + TILE_M) * DIN];   // pre-permuted fp16 x (+pad)
__device__ __half g_wh[LNUM * DIN * DOUT];       // fp16 W

// ---------------- helpers ---------------------------------------------------
__device__ __forceinline__ uint32_t smem_u32(const void* p) {
    uint32_t a;
    asm("{ .reg .u64 t; cvta.to.shared.u64 t, %1; cvt.u32.u64 %0, t; }"
        : "=r"(a) : "l"(p));
    return a;
}
#define CP_ASYNC16(dst, src) \
    asm volatile("cp.async.cg.shared.global [%0], [%1], 16;" :: "r"(dst), "l"(src))
#define CP_COMMIT() asm volatile("cp.async.commit_group;" ::: "memory")
#define CP_WAIT(n)  asm volatile("cp.async.wait_group %0;" :: "n"(n) : "memory")

#define LDSM_X4(r0, r1, r2, r3, a) \
    asm volatile("ldmatrix.sync.aligned.m8n8.x4.shared.b16 {%0,%1,%2,%3}, [%4];" \
                 : "=r"(r0), "=r"(r1), "=r"(r2), "=r"(r3) : "r"(a))
#define LDSM_X4T(r0, r1, r2, r3, a) \
    asm volatile("ldmatrix.sync.aligned.m8n8.x4.trans.shared.b16 {%0,%1,%2,%3}, [%4];" \
                 : "=r"(r0), "=r"(r1), "=r"(r2), "=r"(r3) : "r"(a))
#define MMA16816(d, a, b0, b1)                                               \
    asm volatile("mma.sync.aligned.m16n8k16.row.col.f32.f16.f16.f32 "        \
        "{%0,%1,%2,%3}, {%4,%5,%6,%7}, {%8,%9}, {%0,%1,%2,%3};"              \
        : "+f"((d)[0]), "+f"((d)[1]), "+f"((d)[2]), "+f"((d)[3])             \
        : "r"((a)[0]), "r"((a)[1]), "r"((a)[2]), "r"((a)[3]), "r"(b0), "r"(b1))

// ---------------- planning kernel (single block, warp-aggregated) -----------
__global__ void k_setup(const unsigned* idx_words) {
    __shared__ int      s_cnt[LNUM], s_cur[LNUM], s_off[LNUM + 1];
    __shared__ unsigned s_odd;
    __shared__ int      s_is64;
    const int t = threadIdx.x;   // 1024 threads
    const int lane = t & 31;

    if (t < LNUM) { s_cnt[t] = 0; s_cur[t] = 0; }
    if (t == 0) s_odd = 0u;
    __syncthreads();

    // int64 vs int32 detect: int64 little-endian high words (odd u32) all zero
    unsigned acc = 0;
    for (int j = 1 + 2 * t; j < BTOK; j += 2048) acc |= idx_words[j];
    if (acc) atomicOr(&s_odd, acc);
    __syncthreads();
    if (t == 0) s_is64 = (s_odd == 0u);
    __syncthreads();
    const int is64 = s_is64;

    // histogram: one atomic per (warp, expert) via match_any aggregation
    for (int j = t; j < BTOK; j += 1024) {
        int e = is64 ? (int)((const long long*)idx_words)[j]
                     : ((const int*)idx_words)[j];
        unsigned mask = __match_any_sync(0xffffffffu, e);
        int leader = __ffs(mask) - 1;
        if (lane == leader) atomicAdd(&s_cnt[e], __popc(mask));
    }
    __syncthreads();

    if (t == 0) {
        s_off[0] = 0;
        for (int e = 0; e < LNUM; e++) s_off[e + 1] = s_off[e] + s_cnt[e];
        for (int e = 0; e <= LNUM; e++) g_offsets[e] = s_off[e];
        int nt = 0;
        for (int e = 0; e < LNUM; e++)
            for (int r = s_off[e]; r < s_off[e + 1]; r += TILE_M) {
                g_tile_expert[nt] = e; g_tile_row[nt] = r; nt++;
            }
        g_ntiles = nt;
    }
    __syncthreads();

    // scatter: aggregated base + in-warp rank
    for (int j = t; j < BTOK; j += 1024) {
        int e = is64 ? (int)((const long long*)idx_words)[j]
                     : ((const int*)idx_words)[j];
        unsigned mask = __match_any_sync(0xffffffffu, e);
        int leader = __ffs(mask) - 1;
        int rank   = __popc(mask & ((1u << lane) - 1u));
        int base   = 0;
        if (lane == leader) base = atomicAdd(&s_cur[e], __popc(mask));
        base = __shfl_sync(0xffffffffu, base, leader);
        g_perm[s_off[e] + base + rank] = j;
    }
}

// ---------------- fused fp32 -> fp16 converter ------------------------------
#define W_BLOCKS ((LNUM * DIN * DOUT) / 2048)    // 8192
__global__ void k_convert(const float* __restrict__ W, const float* __restrict__ x) {
    const int b = blockIdx.x;
    const float* src;
    __half* dst;
    if (b < W_BLOCKS) {
        size_t i = (size_t)b * 2048 + threadIdx.x * 8;
        src = W + i;
        dst = g_wh + i;
    } else {
        int p = b - W_BLOCKS;
        int j = g_perm[p];
        src = x + (size_t)j * DIN + threadIdx.x * 8;
        dst = g_xh + (size_t)p * DIN + threadIdx.x * 8;
    }
    float4 a = *(const float4*)src;
    float4 c = *(const float4*)(src + 4);
    __half2 h[4];
    h[0] = __floats2half2_rn(a.x, a.y);
    h[1] = __floats2half2_rn(a.z, a.w);
    h[2] = __floats2half2_rn(c.x, c.y);
    h[3] = __floats2half2_rn(c.z, c.w);
    *(uint4*)dst = *(uint4*)h;
}

// ---------------- GEMM: mma.sync fp16, K-tile 64, 3-stage cp.async ----------
#define A_STG   16384
#define B_STG   16384
#define STG     (A_STG + B_STG)               // 32768
#define SMEM_TOTAL (NSTAGES * STG)            // 98304

__global__ void __launch_bounds__(256, 2)
gemm_kernel(const float* __restrict__ bias, float* __restrict__ out) {
    const int t = blockIdx.x;
    if (t >= g_ntiles) return;

    extern __shared__ char smem[];
    const uint32_t sb = smem_u32(smem);
    const int tid    = threadIdx.x;
    const int lane   = tid & 31;
    const int wid    = tid >> 5;
    const int warp_m = wid & 3;               // 4 warps in M
    const int warp_n = wid >> 2;              // 2 warps in N

    const int e      = g_tile_expert[t];
    const int row0   = g_tile_row[t];
    const int endRow = g_offsets[e + 1];
    const int n0     = blockIdx.y * TILE_N;

    // ---- cp.async per-thread plumbing (4 A + 4 B 16B copies per stage) ----
    const __half* asrc[4];
    const __half* bsrc[4];
    uint32_t adst[4], bdst[4];
    {
        const __half* xbase = g_xh + (size_t)row0 * DIN;
        const __half* wbase = g_wh + (size_t)e * DIN * DOUT + n0;
#pragma unroll
        for (int p = 0; p < 4; p++) {
            int s = tid + p * 256;            // A slot: r = s>>3, c = s&7
            int r = s >> 3, c = s & 7;
            asrc[p] = xbase + (size_t)r * DIN + c * 8;
            adst[p] = (uint32_t)(r * 128 + ((c ^ (r & 7)) << 4));
            int kr = s >> 4, cb = s & 15;     // B slot
            bsrc[p] = wbase + (size_t)kr * DOUT + cb * 8;
            bdst[p] = (uint32_t)(A_STG + kr * 256 +
                                 ((((cb & 7) ^ (kr & 7)) | (cb & 8)) << 4));
        }
    }
    auto issue_stage = [&](int buf) {
        uint32_t base = sb + buf * STG;
#pragma unroll
        for (int p = 0; p < 4; p++) CP_ASYNC16(base + adst[p], asrc[p]);
#pragma unroll
        for (int p = 0; p < 4; p++) CP_ASYNC16(base + bdst[p], bsrc[p]);
#pragma unroll
        for (int p = 0; p < 4; p++) { asrc[p] += TILE_K; bsrc[p] += (size_t)TILE_K * DOUT; }
    };

    // ---- ldmatrix per-lane address components ----
    const int l15 = lane & 15, lhi = lane >> 4, l7 = lane & 7;
    uint32_t aRow[2];
#pragma unroll
    for (int m = 0; m < 2; m++)
        aRow[m] = (uint32_t)((warp_m * 32 + m * 16 + l15) * 128);
    const uint32_t bRowOff = (uint32_t)(A_STG + l15 * 256);
    uint32_t bChunk[4];
#pragma unroll
    for (int f = 0; f < 4; f++)
        bChunk[f] = (uint32_t)(((((2 * f + lhi) ^ l7)) | (warp_n * 8)) << 4);
    uint32_t aChunk[4][2];
#pragma unroll
    for (int s = 0; s < 4; s++)
#pragma unroll
        for (int m = 0; m < 2; m++)
            aChunk[s][m] = aRow[m] + (uint32_t)(((2 * s + lhi) ^ l7) << 4);

    float acc[2][8][4];
#pragma unroll
    for (int m = 0; m < 2; m++)
#pragma unroll
        for (int n = 0; n < 8; n++)
#pragma unroll
            for (int q = 0; q < 4; q++) acc[m][n][q] = 0.0f;

    issue_stage(0); CP_COMMIT();
    issue_stage(1); CP_COMMIT();

#pragma unroll 3
    for (int i = 0; i < NKT; i++) {
        const int buf = i % NSTAGES;
        CP_WAIT(1);
        __syncthreads();
        const uint32_t base = sb + buf * STG;

#pragma unroll
        for (int s = 0; s < 4; s++) {
            uint32_t a[2][4];
#pragma unroll
            for (int m = 0; m < 2; m++)
                LDSM_X4(a[m][0], a[m][1], a[m][2], a[m][3], base + aChunk[s][m]);
            const uint32_t brow = base + bRowOff + s * 4096;
#pragma unroll
            for (int f = 0; f < 4; f++) {
                uint32_t b0, b1, b2, b3;
                LDSM_X4T(b0, b1, b2, b3, brow + bChunk[f]);
                MMA16816(acc[0][2 * f],     a[0], b0, b1);
                MMA16816(acc[1][2 * f],     a[1], b0, b1);
                MMA16816(acc[0][2 * f + 1], a[0], b2, b3);
                MMA16816(acc[1][2 * f + 1], a[1], b2, b3);
            }
            // issue next stage after first sub-step: first LDSM/MMA starts
            // right at the barrier, loads go out under MMA cover. Buffer
            // (i+2)%3 == (i-1)%3, fully consumed before this barrier.
            if (s == 0) {
                if (i + 2 < NKT) issue_stage((i + 2) % NSTAGES);
                CP_COMMIT();
            }
        }
    }

    // ---- epilogue: register-direct stores, bias via cached loads ----------
    // thread holds rows {r0, r0+8, r0+16, r0+24}, cols warp_n*64+n*8+(lane&3)*2
    const int r0 = warp_m * 32 + (lane >> 2);
    int  tok[4];
    bool ok[4];
#pragma unroll
    for (int q = 0; q < 4; q++) {
        int r = row0 + r0 + q * 8;
        ok[q]  = r < endRow;
        tok[q] = ok[q] ? g_perm[r] : 0;
    }
    const float* bcol = bias + (size_t)e * DOUT + n0 + warp_n * 64 + (lane & 3) * 2;
#pragma unroll
    for (int m = 0; m < 2; m++)
#pragma unroll
        for (int n = 0; n < 8; n++) {
            float2 bb = *(const float2*)(bcol + n * 8);
            int col = n0 + warp_n * 64 + n * 8 + (lane & 3) * 2;
            if (ok[m * 2])
                *(float2*)(out + (size_t)tok[m * 2] * DOUT + col) =
                    make_float2(acc[m][n][0] + bb.x, acc[m][n][1] + bb.y);
            if (ok[m * 2 + 1])
                *(float2*)(out + (size_t)tok[m * 2 + 1] * DOUT + col) =
                    make_float2(acc[m][n][2] + bb.x, acc[m][n][3] + bb.y);
        }
}

// ---------------- launch ----------------------------------------------------
extern "C" void kernel_launch(void* const* d_in, const int* in_sizes, int n_in,
                              void* d_out, int out_size) {
    const float* x   = (const float*)d_in[0];
    const void*  idx = d_in[1];
    const float* W   = (const float*)d_in[2];
    const float* b   = (const float*)d_in[3];
    float* out = (float*)d_out;

    cudaFuncSetAttribute(gemm_kernel,
                         cudaFuncAttributeMaxDynamicSharedMemorySize, SMEM_TOTAL);

    k_setup<<<1, 1024>>>((const unsigned*)idx);                 // launch 1
    k_convert<<<W_BLOCKS + BTOK, 256>>>(W, x);                  // launch 2
    dim3 grid(MAX_TILES, DOUT / TILE_N);
    gemm_kernel<<<grid, 256, SMEM_TOTAL>>>(b, out);             // launch 3
}

// round 7
// speedup vs baseline: 5.5743x; 1.0049x over previous
#include <cuda_runtime.h>
#include <cuda_fp16.h>
#include <cstdint>

#define LNUM   4
#define BTOK   16384
#define DIN    2048
#define DOUT   2048
#define TILE_M 128
#define TILE_N 128
#define TILE_K 64
#define NKT    (DIN / TILE_K)                 // 32
#define MAX_TILES (BTOK / TILE_M + LNUM)      // 132
#define NSTAGES 3

// ---------------- scratch (device globals; no allocation allowed) ----------
__device__ int      g_cnt32[LNUM], g_cnt64[LNUM], g_cursor[LNUM];
__device__ unsigned g_odd_or;
__device__ int      g_is64;
__device__ int      g_offsets[LNUM + 1];
__device__ int      g_perm[BTOK];
__device__ int      g_tile_expert[MAX_TILES];
__device__ int      g_tile_row[MAX_TILES];
__device__ int      g_ntiles;
__device__ __half   g_xh[(BTOK + TILE_M) * DIN];   // pre-permuted fp16 x (+pad)
__device__ __half   g_wh[LNUM * DIN * DOUT];       // fp16 W

// ---------------- helpers ---------------------------------------------------
__device__ __forceinline__ uint32_t smem_u32(const void* p) {
    uint32_t a;
    asm("{ .reg .u64 t; cvta.to.shared.u64 t, %1; cvt.u32.u64 %0, t; }"
        : "=r"(a) : "l"(p));
    return a;
}
#define CP_ASYNC16(dst, src) \
    asm volatile("cp.async.cg.shared.global [%0], [%1], 16;" :: "r"(dst), "l"(src))
#define CP_COMMIT() asm volatile("cp.async.commit_group;" ::: "memory")
#define CP_WAIT(n)  asm volatile("cp.async.wait_group %0;" :: "n"(n) : "memory")

#define LDSM_X4(r0, r1, r2, r3, a) \
    asm volatile("ldmatrix.sync.aligned.m8n8.x4.shared.b16 {%0,%1,%2,%3}, [%4];" \
                 : "=r"(r0), "=r"(r1), "=r"(r2), "=r"(r3) : "r"(a))
#define LDSM_X4T(r0, r1, r2, r3, a) \
    asm volatile("ldmatrix.sync.aligned.m8n8.x4.trans.shared.b16 {%0,%1,%2,%3}, [%4];" \
                 : "=r"(r0), "=r"(r1), "=r"(r2), "=r"(r3) : "r"(a))
#define MMA16816(d, a, b0, b1)                                               \
    asm volatile("mma.sync.aligned.m16n8k16.row.col.f32.f16.f16.f32 "        \
        "{%0,%1,%2,%3}, {%4,%5,%6,%7}, {%8,%9}, {%0,%1,%2,%3};"              \
        : "+f"((d)[0]), "+f"((d)[1]), "+f"((d)[2]), "+f"((d)[3])             \
        : "r"((a)[0]), "r"((a)[1]), "r"((a)[2]), "r"((a)[3]), "r"(b0), "r"(b1))

// ---------------- planning kernels (multi-block) -----------------------------
__global__ void k_init() {
    int t = threadIdx.x;
    if (t < LNUM) { g_cnt32[t] = 0; g_cnt64[t] = 0; g_cursor[t] = 0; }
    if (t == 0) g_odd_or = 0u;
}

// One pass: both dtype-interpretation histograms + int64 high-word OR.
// Word j (j < BTOK) exists in both layouts; expert values masked to [0,4).
__global__ void k_hist(const unsigned* __restrict__ w) {
    const int j    = blockIdx.x * blockDim.x + threadIdx.x;   // 16384 threads
    const int lane = threadIdx.x & 31;
    unsigned lo = w[2 * j], hi = w[2 * j + 1];                // int64 view
    unsigned v  = w[j];                                       // int32 view
    if (hi) atomicOr(&g_odd_or, hi);

    int e64 = (int)(lo & 3u);
    unsigned m64 = __match_any_sync(0xffffffffu, e64);
    if (lane == (__ffs(m64) - 1)) atomicAdd(&g_cnt64[e64], __popc(m64));

    int e32 = (int)(v & 3u);
    unsigned m32 = __match_any_sync(0xffffffffu, e32);
    if (lane == (__ffs(m32) - 1)) atomicAdd(&g_cnt32[e32], __popc(m32));
}

__global__ void k_plan() {
    int is64 = (g_odd_or == 0u);
    g_is64 = is64;
    const int* cnt = is64 ? g_cnt64 : g_cnt32;
    g_offsets[0] = 0;
    for (int e = 0; e < LNUM; e++) g_offsets[e + 1] = g_offsets[e] + cnt[e];
    int nt = 0;
    for (int e = 0; e < LNUM; e++)
        for (int r = g_offsets[e]; r < g_offsets[e + 1]; r += TILE_M) {
            g_tile_expert[nt] = e; g_tile_row[nt] = r; nt++;
        }
    g_ntiles = nt;
}

__global__ void k_scatter(const unsigned* __restrict__ w) {
    const int j    = blockIdx.x * blockDim.x + threadIdx.x;
    const int lane = threadIdx.x & 31;
    int e = g_is64 ? (int)(w[2 * j] & 3u) : (int)(w[j] & 3u);
    unsigned mask = __match_any_sync(0xffffffffu, e);
    int leader = __ffs(mask) - 1;
    int rank   = __popc(mask & ((1u << lane) - 1u));
    int base   = 0;
    if (lane == leader) base = atomicAdd(&g_cursor[e], __popc(mask));
    base = __shfl_sync(0xffffffffu, base, leader);
    g_perm[g_offsets[e] + base + rank] = j;
}

// ---------------- fused fp32 -> fp16 converter ------------------------------
#define W_BLOCKS ((LNUM * DIN * DOUT) / 2048)    // 8192
__global__ void k_convert(const float* __restrict__ W, const float* __restrict__ x) {
    const int b = blockIdx.x;
    const float* src;
    __half* dst;
    if (b < W_BLOCKS) {
        size_t i = (size_t)b * 2048 + threadIdx.x * 8;
        src = W + i;
        dst = g_wh + i;
    } else {
        int p = b - W_BLOCKS;
        int j = g_perm[p];
        src = x + (size_t)j * DIN + threadIdx.x * 8;
        dst = g_xh + (size_t)p * DIN + threadIdx.x * 8;
    }
    float4 a = *(const float4*)src;
    float4 c = *(const float4*)(src + 4);
    __half2 h[4];
    h[0] = __floats2half2_rn(a.x, a.y);
    h[1] = __floats2half2_rn(a.z, a.w);
    h[2] = __floats2half2_rn(c.x, c.y);
    h[3] = __floats2half2_rn(c.z, c.w);
    *(uint4*)dst = *(uint4*)h;
}

// ---------------- GEMM: mma.sync fp16, K-tile 64, 3-stage cp.async ----------
#define A_STG   16384
#define B_STG   16384
#define STG     (A_STG + B_STG)               // 32768
#define SMEM_TOTAL (NSTAGES * STG)            // 98304

__global__ void __launch_bounds__(256, 2)
gemm_kernel(const float* __restrict__ bias, float* __restrict__ out) {
    const int t = blockIdx.x;
    if (t >= g_ntiles) return;

    extern __shared__ char smem[];
    const uint32_t sb = smem_u32(smem);
    const int tid    = threadIdx.x;
    const int lane   = tid & 31;
    const int wid    = tid >> 5;
    const int warp_m = wid & 3;               // 4 warps in M
    const int warp_n = wid >> 2;              // 2 warps in N

    const int e      = g_tile_expert[t];
    const int row0   = g_tile_row[t];
    const int endRow = g_offsets[e + 1];
    const int n0     = blockIdx.y * TILE_N;

    // ---- cp.async per-thread plumbing (4 A + 4 B 16B copies per stage) ----
    const __half* asrc[4];
    const __half* bsrc[4];
    uint32_t adst[4], bdst[4];
    {
        const __half* xbase = g_xh + (size_t)row0 * DIN;
        const __half* wbase = g_wh + (size_t)e * DIN * DOUT + n0;
#pragma unroll
        for (int p = 0; p < 4; p++) {
            int s = tid + p * 256;            // A slot: r = s>>3, c = s&7
            int r = s >> 3, c = s & 7;
            asrc[p] = xbase + (size_t)r * DIN + c * 8;
            adst[p] = (uint32_t)(r * 128 + ((c ^ (r & 7)) << 4));
            int kr = s >> 4, cb = s & 15;     // B slot
            bsrc[p] = wbase + (size_t)kr * DOUT + cb * 8;
            bdst[p] = (uint32_t)(A_STG + kr * 256 +
                                 ((((cb & 7) ^ (kr & 7)) | (cb & 8)) << 4));
        }
    }
    auto issue_stage = [&](int buf) {
        uint32_t base = sb + buf * STG;
#pragma unroll
        for (int p = 0; p < 4; p++) CP_ASYNC16(base + adst[p], asrc[p]);
#pragma unroll
        for (int p = 0; p < 4; p++) CP_ASYNC16(base + bdst[p], bsrc[p]);
#pragma unroll
        for (int p = 0; p < 4; p++) { asrc[p] += TILE_K; bsrc[p] += (size_t)TILE_K * DOUT; }
    };

    // ---- ldmatrix per-lane address components ----
    const int l15 = lane & 15, lhi = lane >> 4, l7 = lane & 7;
    uint32_t aRow[2];
#pragma unroll
    for (int m = 0; m < 2; m++)
        aRow[m] = (uint32_t)((warp_m * 32 + m * 16 + l15) * 128);
    const uint32_t bRowOff = (uint32_t)(A_STG + l15 * 256);
    uint32_t bChunk[4];
#pragma unroll
    for (int f = 0; f < 4; f++)
        bChunk[f] = (uint32_t)(((((2 * f + lhi) ^ l7)) | (warp_n * 8)) << 4);
    uint32_t aChunk[4][2];
#pragma unroll
    for (int s = 0; s < 4; s++)
#pragma unroll
        for (int m = 0; m < 2; m++)
            aChunk[s][m] = aRow[m] + (uint32_t)(((2 * s + lhi) ^ l7) << 4);

    float acc[2][8][4];
#pragma unroll
    for (int m = 0; m < 2; m++)
#pragma unroll
        for (int n = 0; n < 8; n++)
#pragma unroll
            for (int q = 0; q < 4; q++) acc[m][n][q] = 0.0f;

    issue_stage(0); CP_COMMIT();
    issue_stage(1); CP_COMMIT();

#pragma unroll 3
    for (int i = 0; i < NKT; i++) {
        const int buf = i % NSTAGES;
        CP_WAIT(1);
        __syncthreads();
        const uint32_t base = sb + buf * STG;

#pragma unroll
        for (int s = 0; s < 4; s++) {
            uint32_t a[2][4];
#pragma unroll
            for (int m = 0; m < 2; m++)
                LDSM_X4(a[m][0], a[m][1], a[m][2], a[m][3], base + aChunk[s][m]);
            const uint32_t brow = base + bRowOff + s * 4096;

            // B double-buffered: LDSM for f+1 issues before MMAs consuming f
            uint32_t b[2][4];
            LDSM_X4T(b[0][0], b[0][1], b[0][2], b[0][3], brow + bChunk[0]);
#pragma unroll
            for (int f = 0; f < 4; f++) {
                const int cur = f & 1;
                if (f < 3)
                    LDSM_X4T(b[cur ^ 1][0], b[cur ^ 1][1],
                             b[cur ^ 1][2], b[cur ^ 1][3], brow + bChunk[f + 1]);
                MMA16816(acc[0][2 * f],     a[0], b[cur][0], b[cur][1]);
                MMA16816(acc[1][2 * f],     a[1], b[cur][0], b[cur][1]);
                MMA16816(acc[0][2 * f + 1], a[0], b[cur][2], b[cur][3]);
                MMA16816(acc[1][2 * f + 1], a[1], b[cur][2], b[cur][3]);
            }
            // next-stage loads go out under MMA cover; buffer (i+2)%3 ==
            // (i-1)%3, fully consumed before this iteration's barrier.
            if (s == 0) {
                if (i + 2 < NKT) issue_stage((i + 2) % NSTAGES);
                CP_COMMIT();
            }
        }
    }

    // ---- epilogue: register-direct stores, bias via cached loads ----------
    const int r0 = warp_m * 32 + (lane >> 2);
    int  tok[4];
    bool ok[4];
#pragma unroll
    for (int q = 0; q < 4; q++) {
        int r = row0 + r0 + q * 8;
        ok[q]  = r < endRow;
        tok[q] = ok[q] ? g_perm[r] : 0;
    }
    const float* bcol = bias + (size_t)e * DOUT + n0 + warp_n * 64 + (lane & 3) * 2;
#pragma unroll
    for (int m = 0; m < 2; m++)
#pragma unroll
        for (int n = 0; n < 8; n++) {
            float2 bb = *(const float2*)(bcol + n * 8);
            int col = n0 + warp_n * 64 + n * 8 + (lane & 3) * 2;
            if (ok[m * 2])
                *(float2*)(out + (size_t)tok[m * 2] * DOUT + col) =
                    make_float2(acc[m][n][0] + bb.x, acc[m][n][1] + bb.y);
            if (ok[m * 2 + 1])
                *(float2*)(out + (size_t)tok[m * 2 + 1] * DOUT + col) =
                    make_float2(acc[m][n][2] + bb.x, acc[m][n][3] + bb.y);
        }
}

// ---------------- launch ----------------------------------------------------
extern "C" void kernel_launch(void* const* d_in, const int* in_sizes, int n_in,
                              void* d_out, int out_size) {
    const float* x   = (const float*)d_in[0];
    const void*  idx = d_in[1];
    const float* W   = (const float*)d_in[2];
    const float* b   = (const float*)d_in[3];
    float* out = (float*)d_out;

    cudaFuncSetAttribute(gemm_kernel,
                         cudaFuncAttributeMaxDynamicSharedMemorySize, SMEM_TOTAL);

    k_init<<<1, 32>>>();
    k_hist<<<BTOK / 256, 256>>>((const unsigned*)idx);
    k_plan<<<1, 1>>>();
    k_scatter<<<BTOK / 256, 256>>>((const unsigned*)idx);
    k_convert<<<W_BLOCKS + BTOK, 256>>>(W, x);
    dim3 grid(MAX_TILES, DOUT / TILE_N);
    gemm_kernel<<<grid, 256, SMEM_TOTAL>>>(b, out);
}